// round 1
// baseline (speedup 1.0000x reference)
#include <cuda_runtime.h>
#include <cuda_bf16.h>

// Problem constants
#define B_DIM 128
#define L_DIM 1024
#define D_DIM 128
#define DV    32          // D / 4 (float4 groups)
#define TSTART 128        // output start positions per tile
#define NPOS  159         // TSTART + 31 halo input positions
#define NS4   156         // TSTART + 28 s4 positions needed
#define NTHREADS 512

// Output row offsets for window sizes 4, 8, 16, 32
#define OFF4  0
#define OFF8  1021
#define OFF16 2038
#define OFF32 3047
#define ROWS  4040

// Shared memory layout (floats):
//   xm  : NPOS * D_DIM           (masked inputs, float4-accessed)
//   s4  : NS4  * D_DIM           (4-wide partial sums)
//   inv : 4 * TSTART             (1/winlen per window per start)
//   msk : NPOS ints
#define SMEM_FLOATS (NPOS * D_DIM + NS4 * D_DIM + 4 * TSTART + 160)
#define SMEM_BYTES  (SMEM_FLOATS * 4)

__device__ __forceinline__ float4 add4(float4 a, float4 b) {
    return make_float4(a.x + b.x, a.y + b.y, a.z + b.z, a.w + b.w);
}

extern __shared__ float smem_raw[];

__global__ __launch_bounds__(NTHREADS, 1)
void msse_kernel(const float* __restrict__ x,
                 const int* __restrict__ mask,
                 float* __restrict__ out)
{
    const int b  = blockIdx.y;
    const int s0 = blockIdx.x * TSTART;       // global start of this tile
    const int tid = threadIdx.x;

    float4* xm  = reinterpret_cast<float4*>(smem_raw);                 // NPOS*DV f4
    float4* s4  = xm + NPOS * DV;                                      // NS4 *DV f4
    float*  inv = reinterpret_cast<float*>(s4 + NS4 * DV);             // 4*TSTART
    int*    msk = reinterpret_cast<int*>(inv + 4 * TSTART);            // NPOS

    // ---- phase 1: load mask tile (with halo), zero-pad past L ----
    const int* mrow = mask + (size_t)b * L_DIM;
    for (int p = tid; p < NPOS; p += NTHREADS) {
        int g = s0 + p;
        msk[p] = (g < L_DIM) ? mrow[g] : 0;
    }
    __syncthreads();

    // ---- phase 2a: load masked x tile into smem (float4), zero-pad ----
    const float4* xrow = reinterpret_cast<const float4*>(x + (size_t)b * L_DIM * D_DIM);
    for (int i = tid; i < NPOS * DV; i += NTHREADS) {
        int p = i >> 5;            // position in tile
        int q = i & 31;            // float4 group in D
        int g = s0 + p;
        float4 v = make_float4(0.f, 0.f, 0.f, 0.f);
        if (g < L_DIM && msk[p]) {
            v = xrow[g * DV + q];
        }
        xm[i] = v;
    }

    // ---- phase 2b: per-start window-length reciprocals (scalar, shared by all d) ----
    if (tid < TSTART) {
        int j = tid;
        int c = 0;
        #pragma unroll
        for (int k = 0; k < 4; k++)  c += msk[j + k];
        int c4 = c;
        #pragma unroll
        for (int k = 4; k < 8; k++)  c += msk[j + k];
        int c8 = c;
        #pragma unroll
        for (int k = 8; k < 16; k++) c += msk[j + k];
        int c16 = c;
        #pragma unroll
        for (int k = 16; k < 32; k++) c += msk[j + k];
        int c32 = c;
        inv[0 * TSTART + j] = 1.0f / (float)(c4  > 1 ? c4  : 1);
        inv[1 * TSTART + j] = 1.0f / (float)(c8  > 1 ? c8  : 1);
        inv[2 * TSTART + j] = 1.0f / (float)(c16 > 1 ? c16 : 1);
        inv[3 * TSTART + j] = 1.0f / (float)(c32 > 1 ? c32 : 1);
    }
    __syncthreads();

    // ---- phase 3: build s4[p] = xm[p] + xm[p+1] + xm[p+2] + xm[p+3] ----
    for (int i = tid; i < NS4 * DV; i += NTHREADS) {
        int p = i >> 5;
        int q = i & 31;
        float4 a = xm[(p    ) * DV + q];
        float4 b4 = xm[(p + 1) * DV + q];
        float4 c4v = xm[(p + 2) * DV + q];
        float4 d4 = xm[(p + 3) * DV + q];
        s4[i] = add4(add4(a, b4), add4(c4v, d4));
    }
    __syncthreads();

    // ---- phase 4: compute all 4 window outputs per (start j, d-group q) ----
    float4* outb = reinterpret_cast<float4*>(out + (size_t)b * ROWS * D_DIM);
    for (int it = tid; it < TSTART * DV; it += NTHREADS) {
        int j = it >> 5;          // local start; whole warp shares j -> coalesced rows
        int q = it & 31;
        int gi = s0 + j;          // global start index

        float4 a0 = s4[(j     ) * DV + q];
        float4 a1 = s4[(j +  4) * DV + q];
        float4 a2 = s4[(j +  8) * DV + q];
        float4 a3 = s4[(j + 12) * DV + q];
        float4 a4 = s4[(j + 16) * DV + q];
        float4 a5 = s4[(j + 20) * DV + q];
        float4 a6 = s4[(j + 24) * DV + q];
        float4 a7 = s4[(j + 28) * DV + q];

        float4 sum8  = add4(a0, a1);
        float4 sum16 = add4(sum8, add4(a2, a3));
        float4 sum32 = add4(sum16, add4(add4(a4, a5), add4(a6, a7)));

        float i4  = inv[0 * TSTART + j];
        float i8  = inv[1 * TSTART + j];
        float i16 = inv[2 * TSTART + j];
        float i32 = inv[3 * TSTART + j];

        if (gi <= L_DIM - 4) {
            outb[(OFF4  + gi) * DV + q] = make_float4(a0.x * i4,  a0.y * i4,  a0.z * i4,  a0.w * i4);
        }
        if (gi <= L_DIM - 8) {
            outb[(OFF8  + gi) * DV + q] = make_float4(sum8.x * i8,  sum8.y * i8,  sum8.z * i8,  sum8.w * i8);
        }
        if (gi <= L_DIM - 16) {
            outb[(OFF16 + gi) * DV + q] = make_float4(sum16.x * i16, sum16.y * i16, sum16.z * i16, sum16.w * i16);
        }
        if (gi <= L_DIM - 32) {
            outb[(OFF32 + gi) * DV + q] = make_float4(sum32.x * i32, sum32.y * i32, sum32.z * i32, sum32.w * i32);
        }
    }
}

extern "C" void kernel_launch(void* const* d_in, const int* in_sizes, int n_in,
                              void* d_out, int out_size)
{
    const float* x    = (const float*)d_in[0];
    const int*   mask = (const int*)d_in[1];
    float*       out  = (float*)d_out;

    cudaFuncSetAttribute(msse_kernel,
                         cudaFuncAttributeMaxDynamicSharedMemorySize, SMEM_BYTES);

    dim3 grid(8, B_DIM);   // 8 start-tiles of 128 cover starts 0..1023
    msse_kernel<<<grid, NTHREADS, SMEM_BYTES>>>(x, mask, out);
}

// round 2
// speedup vs baseline: 1.3634x; 1.3634x over previous
#include <cuda_runtime.h>
#include <cuda_bf16.h>

// Problem constants
#define B_DIM 128
#define L_DIM 1024
#define D_DIM 128
#define DVF   32          // D / 4 (float4 groups, full)
#define DT    8           // float4 groups per D-tile (D split 4-ways)
#define NDT   4           // number of D tiles
#define TSTART 128        // output start positions per tile
#define NPOS  159         // TSTART + 31 halo input positions
#define NS4   156         // TSTART + 28 sliding-4-sum positions needed
#define NTHREADS 512

// Output row offsets for window sizes 4, 8, 16, 32
#define OFF4  0
#define OFF8  1021
#define OFF16 2038
#define OFF32 3047
#define ROWS  4040

// Shared memory (floats):
//   xm  : NPOS * DT*4   masked inputs
//   s4  : NS4  * DT*4   sliding 4-sums
//   inv : 4 * TSTART
//   msk : NPOS ints (padded to 160)
#define SMEM_FLOATS (NPOS * DT * 4 + NS4 * DT * 4 + 4 * TSTART + 160)
#define SMEM_BYTES  (SMEM_FLOATS * 4)

__device__ __forceinline__ float4 add4(float4 a, float4 b) {
    return make_float4(a.x + b.x, a.y + b.y, a.z + b.z, a.w + b.w);
}

extern __shared__ float smem_raw[];

__global__ __launch_bounds__(NTHREADS, 4)
void msse_kernel(const float* __restrict__ x,
                 const int* __restrict__ mask,
                 float* __restrict__ out)
{
    const int s0    = blockIdx.x * TSTART;    // global start of this L tile
    const int dbase = blockIdx.y * DT;        // float4-group base of this D tile
    const int b     = blockIdx.z;
    const int tid   = threadIdx.x;

    float4* xm  = reinterpret_cast<float4*>(smem_raw);          // NPOS*DT f4
    float4* s4  = xm + NPOS * DT;                                // NS4 *DT f4
    float*  inv = reinterpret_cast<float*>(s4 + NS4 * DT);       // 4*TSTART
    int*    msk = reinterpret_cast<int*>(inv + 4 * TSTART);      // NPOS

    // ---- phase 1: load mask tile (with halo), zero-pad past L ----
    const int* mrow = mask + (size_t)b * L_DIM;
    for (int p = tid; p < NPOS; p += NTHREADS) {
        int g = s0 + p;
        msk[p] = (g < L_DIM) ? mrow[g] : 0;
    }
    __syncthreads();

    // ---- phase 2a: load masked x D-slice into smem (float4), zero-pad ----
    const float4* xrow = reinterpret_cast<const float4*>(x + (size_t)b * L_DIM * D_DIM);
    for (int i = tid; i < NPOS * DT; i += NTHREADS) {
        int p = i >> 3;            // position in tile
        int q = i & 7;             // float4 group within D tile
        int g = s0 + p;
        float4 v = make_float4(0.f, 0.f, 0.f, 0.f);
        if (g < L_DIM && msk[p]) {
            v = xrow[g * DVF + dbase + q];
        }
        xm[i] = v;
    }

    // ---- phase 2b: per-start window-length reciprocals ----
    if (tid < TSTART) {
        int j = tid;
        int c = 0;
        #pragma unroll
        for (int k = 0; k < 4; k++)  c += msk[j + k];
        int c4 = c;
        #pragma unroll
        for (int k = 4; k < 8; k++)  c += msk[j + k];
        int c8 = c;
        #pragma unroll
        for (int k = 8; k < 16; k++) c += msk[j + k];
        int c16 = c;
        #pragma unroll
        for (int k = 16; k < 32; k++) c += msk[j + k];
        int c32 = c;
        inv[0 * TSTART + j] = 1.0f / (float)(c4  > 1 ? c4  : 1);
        inv[1 * TSTART + j] = 1.0f / (float)(c8  > 1 ? c8  : 1);
        inv[2 * TSTART + j] = 1.0f / (float)(c16 > 1 ? c16 : 1);
        inv[3 * TSTART + j] = 1.0f / (float)(c32 > 1 ? c32 : 1);
    }
    __syncthreads();

    // ---- phase 3: s4[p] = xm[p] + xm[p+1] + xm[p+2] + xm[p+3] ----
    for (int i = tid; i < NS4 * DT; i += NTHREADS) {
        int p = i >> 3;
        int q = i & 7;
        float4 a  = xm[(p    ) * DT + q];
        float4 b4 = xm[(p + 1) * DT + q];
        float4 c4v= xm[(p + 2) * DT + q];
        float4 d4 = xm[(p + 3) * DT + q];
        s4[i] = add4(add4(a, b4), add4(c4v, d4));
    }
    __syncthreads();

    // ---- phase 4: all 4 window outputs per (start j, d-group q) ----
    float4* outb = reinterpret_cast<float4*>(out + (size_t)b * ROWS * D_DIM);
    for (int it = tid; it < TSTART * DT; it += NTHREADS) {
        int j = it >> 3;          // local start; warp shares few j -> coalesced rows
        int q = it & 7;
        int gi = s0 + j;          // global start index
        int oq = dbase + q;       // output float4 column

        float4 a0 = s4[(j     ) * DT + q];
        float4 a1 = s4[(j +  4) * DT + q];
        float4 a2 = s4[(j +  8) * DT + q];
        float4 a3 = s4[(j + 12) * DT + q];
        float4 a4 = s4[(j + 16) * DT + q];
        float4 a5 = s4[(j + 20) * DT + q];
        float4 a6 = s4[(j + 24) * DT + q];
        float4 a7 = s4[(j + 28) * DT + q];

        float4 sum8  = add4(a0, a1);
        float4 sum16 = add4(sum8, add4(a2, a3));
        float4 sum32 = add4(sum16, add4(add4(a4, a5), add4(a6, a7)));

        float i4  = inv[0 * TSTART + j];
        float i8  = inv[1 * TSTART + j];
        float i16 = inv[2 * TSTART + j];
        float i32 = inv[3 * TSTART + j];

        if (gi <= L_DIM - 4) {
            outb[(OFF4  + gi) * DVF + oq] = make_float4(a0.x * i4,  a0.y * i4,  a0.z * i4,  a0.w * i4);
        }
        if (gi <= L_DIM - 8) {
            outb[(OFF8  + gi) * DVF + oq] = make_float4(sum8.x * i8,  sum8.y * i8,  sum8.z * i8,  sum8.w * i8);
        }
        if (gi <= L_DIM - 16) {
            outb[(OFF16 + gi) * DVF + oq] = make_float4(sum16.x * i16, sum16.y * i16, sum16.z * i16, sum16.w * i16);
        }
        if (gi <= L_DIM - 32) {
            outb[(OFF32 + gi) * DVF + oq] = make_float4(sum32.x * i32, sum32.y * i32, sum32.z * i32, sum32.w * i32);
        }
    }
}

extern "C" void kernel_launch(void* const* d_in, const int* in_sizes, int n_in,
                              void* d_out, int out_size)
{
    const float* x    = (const float*)d_in[0];
    const int*   mask = (const int*)d_in[1];
    float*       out  = (float*)d_out;

    cudaFuncSetAttribute(msse_kernel,
                         cudaFuncAttributeMaxDynamicSharedMemorySize, SMEM_BYTES);

    dim3 grid(8, NDT, B_DIM);   // 8 L-tiles x 4 D-tiles x 128 batches
    msse_kernel<<<grid, NTHREADS, SMEM_BYTES>>>(x, mask, out);
}